// round 9
// baseline (speedup 1.0000x reference)
#include <cuda_runtime.h>
#include <math.h>

// Problem constants
#define NFEAT   256
#define BATCH   8192
#define H1DIM   100
#define H2DIM   50
#define W2SZ    (H2DIM * H1DIM)   // 5000

// Tiling: 128 threads, 2 batch rows per thread -> 256 rows per block
#define THREADS          128
#define RPT              2
#define ROWS_PER_BLOCK   (THREADS * RPT)          // 256
#define ROW_TILES        (BATCH / ROWS_PER_BLOCK) // 32
#define FEATS_PER_CHUNK  8
#define FEAT_CHUNKS      (NFEAT / FEATS_PER_CHUNK) // 32
#define W2_STRIDE        52   // padded [h][o] row: 52*4=208B, 16B-aligned rows

// Per-chunk partial sums (written unconditionally each launch -> deterministic)
__device__ float g_partial[FEAT_CHUNKS][BATCH];

struct SmemBuf {
    float  w2t[H1DIM][W2_STRIDE]; // transposed W2: [h][o], o contiguous for f32x2
    float2 w1b1[H1DIM];           // packed (w1[h], b1[h]) -> one LDS.64 per h
    float  b2[H2DIM];             // 8B-aligned
    float  w3[H2DIM];
};

// ---- f32x2 packed helpers (sm_100+ PTX) ----
__device__ __forceinline__ unsigned long long pack2(float v) {
    unsigned long long r;
    asm("mov.b64 %0, {%1, %1};" : "=l"(r) : "f"(v));
    return r;
}
__device__ __forceinline__ void ffma2(unsigned long long& acc,
                                      unsigned long long a,
                                      unsigned long long b) {
    asm("fma.rn.f32x2 %0, %1, %2, %0;" : "+l"(acc) : "l"(a), "l"(b));
}
__device__ __forceinline__ void unpack2(unsigned long long v, float& lo, float& hi) {
    asm("mov.b64 {%0, %1}, %2;" : "=f"(lo), "=f"(hi) : "l"(v));
}

// Stage one feature's weights into a shared buffer (cooperative, coalesced LDG)
__device__ __forceinline__ void stage(SmemBuf& b,
                                      const float* __restrict__ W1f,
                                      const float* __restrict__ b1f,
                                      const float* __restrict__ W2f,
                                      const float* __restrict__ b2f,
                                      const float* __restrict__ W3f,
                                      int tid)
{
    #pragma unroll 4
    for (int i = tid; i < W2SZ; i += THREADS) {
        int o = i / H1DIM;
        int h = i - o * H1DIM;
        b.w2t[h][o] = W2f[i];
    }
    if (tid < H1DIM) {
        b.w1b1[tid] = make_float2(W1f[tid], b1f[tid]);
    }
    if (tid < H2DIM) {
        b.b2[tid] = b2f[tid];
        b.w3[tid] = W3f[tid];
    }
}

// Evaluate one feature's subnet for TWO batch rows sharing each w2 smem load.
// 2x50 h2 accumulators live as 2x25 packed f32x2 pairs, initialized with b2.
__device__ __forceinline__ void feat_eval2(const SmemBuf& b, float xa, float xb,
                                           float& ra, float& rb)
{
    unsigned long long accA[25], accB[25];
    const unsigned long long* b2p = reinterpret_cast<const unsigned long long*>(b.b2);
    #pragma unroll
    for (int p = 0; p < 25; ++p) { accA[p] = b2p[p]; accB[p] = b2p[p]; }

    #pragma unroll 1
    for (int h = 0; h < H1DIM; ++h) {
        float2 wb = b.w1b1[h];
        float h1a = fmaxf(fmaf(xa, wb.x, wb.y), 0.0f);
        float h1b = fmaxf(fmaf(xb, wb.x, wb.y), 0.0f);
        unsigned long long pa = pack2(h1a);
        unsigned long long pb = pack2(h1b);
        const unsigned long long* w2row =
            reinterpret_cast<const unsigned long long*>(&b.w2t[h][0]);
        #pragma unroll
        for (int p = 0; p < 25; ++p) {
            unsigned long long w = w2row[p];   // one LDS.64, reused twice
            ffma2(accA[p], w, pa);
            ffma2(accB[p], w, pb);
        }
    }

    float sa = 0.0f, sb = 0.0f;
    #pragma unroll
    for (int p = 0; p < 25; ++p) {
        float lo, hi;
        float w3lo = b.w3[2 * p], w3hi = b.w3[2 * p + 1];
        unpack2(accA[p], lo, hi);
        sa = fmaf(fmaxf(lo, 0.0f), w3lo, sa);
        sa = fmaf(fmaxf(hi, 0.0f), w3hi, sa);
        unpack2(accB[p], lo, hi);
        sb = fmaf(fmaxf(lo, 0.0f), w3lo, sb);
        sb = fmaf(fmaxf(hi, 0.0f), w3hi, sb);
    }
    ra = sa; rb = sb;
}

__global__ void __launch_bounds__(THREADS, 3)
nam_main(const float* __restrict__ x,  const float* __restrict__ W1,
         const float* __restrict__ b1, const float* __restrict__ W2,
         const float* __restrict__ b2, const float* __restrict__ W3)
{
    __shared__ SmemBuf sb[2];

    const int tid  = threadIdx.x;
    const int rowA = blockIdx.x * ROWS_PER_BLOCK + tid;           // rows strided by 128
    const int rowB = rowA + THREADS;
    const int f0   = blockIdx.y * FEATS_PER_CHUNK;
    const float* xrowA = x + (long)rowA * NFEAT + f0;
    const float* xrowB = x + (long)rowB * NFEAT + f0;

    // prologue: stage feature f0 into buffer 0
    stage(sb[0], W1 + f0 * H1DIM, b1 + f0 * H1DIM, W2 + (long)f0 * W2SZ,
          b2 + f0 * H2DIM, W3 + f0 * H2DIM, tid);
    __syncthreads();

    float accA = 0.0f, accB = 0.0f;
    #pragma unroll 1
    for (int k = 0; k < FEATS_PER_CHUNK; ++k) {
        // stage next feature into the other buffer (hidden under compute)
        if (k + 1 < FEATS_PER_CHUNK) {
            int f = f0 + k + 1;
            stage(sb[(k + 1) & 1], W1 + f * H1DIM, b1 + f * H1DIM,
                  W2 + (long)f * W2SZ, b2 + f * H2DIM, W3 + f * H2DIM, tid);
        }
        float ra, rb;
        feat_eval2(sb[k & 1], xrowA[k], xrowB[k], ra, rb);
        accA += ra;
        accB += rb;
        __syncthreads();
    }

    g_partial[blockIdx.y][rowA] = accA;
    g_partial[blockIdx.y][rowB] = accB;
}

__global__ void nam_reduce(const float* __restrict__ bias, float* __restrict__ out)
{
    int b = blockIdx.x * 256 + threadIdx.x;
    if (b < BATCH) {
        float s = bias[0];
        #pragma unroll
        for (int c = 0; c < FEAT_CHUNKS; ++c) s += g_partial[c][b];
        out[b] = 1.0f / (1.0f + expf(-s));
    }
}

extern "C" void kernel_launch(void* const* d_in, const int* in_sizes, int n_in,
                              void* d_out, int out_size)
{
    const float* x    = (const float*)d_in[0];  // [8192,256]
    const float* W1   = (const float*)d_in[1];  // [256,100]
    const float* b1   = (const float*)d_in[2];  // [256,100]
    const float* W2   = (const float*)d_in[3];  // [256,50,100]
    const float* b2   = (const float*)d_in[4];  // [256,50]
    const float* W3   = (const float*)d_in[5];  // [256,50]
    const float* bias = (const float*)d_in[6];  // [1]
    float* out = (float*)d_out;                 // [8192]

    dim3 grid(ROW_TILES, FEAT_CHUNKS);
    nam_main<<<grid, THREADS>>>(x, W1, b1, W2, b2, W3);
    nam_reduce<<<BATCH / 256, 256>>>(bias, out);
}

// round 10
// speedup vs baseline: 1.0039x; 1.0039x over previous
#include <cuda_runtime.h>
#include <math.h>

// Problem constants
#define NFEAT   256
#define BATCH   8192
#define H1DIM   100
#define H2DIM   50
#define W2SZ    (H2DIM * H1DIM)   // 5000

// Tiling: 128 threads, 2 batch rows per thread -> 256 rows per block
#define THREADS          128
#define RPT              2
#define ROWS_PER_BLOCK   (THREADS * RPT)          // 256
#define ROW_TILES        (BATCH / ROWS_PER_BLOCK) // 32
#define FEATS_PER_CHUNK  8
#define FEAT_CHUNKS      (NFEAT / FEATS_PER_CHUNK) // 32
#define W2_STRIDE        52   // padded [h][o] row: 52*4=208B, 16B-aligned rows

// Per-chunk partial sums (written unconditionally each launch -> deterministic)
__device__ float g_partial[FEAT_CHUNKS][BATCH];

struct SmemBuf {
    float  w2t[H1DIM][W2_STRIDE]; // transposed W2: [h][o], o contiguous for f32x2
    float2 w1b1[H1DIM];           // packed (w1[h], b1[h]) -> one LDS.64 per h
    float  b2[H2DIM];             // 8B-aligned
    float  w3[H2DIM];
};

// ---- f32x2 packed helpers (sm_100+ PTX) ----
__device__ __forceinline__ unsigned long long pack2(float v) {
    unsigned long long r;
    asm("mov.b64 %0, {%1, %1};" : "=l"(r) : "f"(v));
    return r;
}
__device__ __forceinline__ void ffma2(unsigned long long& acc,
                                      unsigned long long a,
                                      unsigned long long b) {
    asm("fma.rn.f32x2 %0, %1, %2, %0;" : "+l"(acc) : "l"(a), "l"(b));
}
__device__ __forceinline__ void unpack2(unsigned long long v, float& lo, float& hi) {
    asm("mov.b64 {%0, %1}, %2;" : "=f"(lo), "=f"(hi) : "l"(v));
}

// Stage one feature's weights into a shared buffer (cooperative, coalesced LDG)
__device__ __forceinline__ void stage(SmemBuf& b,
                                      const float* __restrict__ W1f,
                                      const float* __restrict__ b1f,
                                      const float* __restrict__ W2f,
                                      const float* __restrict__ b2f,
                                      const float* __restrict__ W3f,
                                      int tid)
{
    #pragma unroll 4
    for (int i = tid; i < W2SZ; i += THREADS) {
        int o = i / H1DIM;
        int h = i - o * H1DIM;
        b.w2t[h][o] = W2f[i];
    }
    if (tid < H1DIM) {
        b.w1b1[tid] = make_float2(W1f[tid], b1f[tid]);
    }
    if (tid < H2DIM) {
        b.b2[tid] = b2f[tid];
        b.w3[tid] = W3f[tid];
    }
}

// Evaluate one feature's subnet for TWO batch rows sharing each w2 smem load.
// 2x50 h2 accumulators live as 2x25 packed f32x2 pairs, initialized with b2.
__device__ __forceinline__ void feat_eval2(const SmemBuf& b, float xa, float xb,
                                           float& ra, float& rb)
{
    unsigned long long accA[25], accB[25];
    const unsigned long long* b2p = reinterpret_cast<const unsigned long long*>(b.b2);
    #pragma unroll
    for (int p = 0; p < 25; ++p) { accA[p] = b2p[p]; accB[p] = b2p[p]; }

    #pragma unroll 1
    for (int h = 0; h < H1DIM; ++h) {
        float2 wb = b.w1b1[h];
        float h1a = fmaxf(fmaf(xa, wb.x, wb.y), 0.0f);
        float h1b = fmaxf(fmaf(xb, wb.x, wb.y), 0.0f);
        unsigned long long pa = pack2(h1a);
        unsigned long long pb = pack2(h1b);
        const unsigned long long* w2row =
            reinterpret_cast<const unsigned long long*>(&b.w2t[h][0]);
        #pragma unroll
        for (int p = 0; p < 25; ++p) {
            unsigned long long w = w2row[p];   // one LDS.64, reused twice
            ffma2(accA[p], w, pa);
            ffma2(accB[p], w, pb);
        }
    }

    float sa = 0.0f, sb = 0.0f;
    #pragma unroll
    for (int p = 0; p < 25; ++p) {
        float lo, hi;
        float w3lo = b.w3[2 * p], w3hi = b.w3[2 * p + 1];
        unpack2(accA[p], lo, hi);
        sa = fmaf(fmaxf(lo, 0.0f), w3lo, sa);
        sa = fmaf(fmaxf(hi, 0.0f), w3hi, sa);
        unpack2(accB[p], lo, hi);
        sb = fmaf(fmaxf(lo, 0.0f), w3lo, sb);
        sb = fmaf(fmaxf(hi, 0.0f), w3hi, sb);
    }
    ra = sa; rb = sb;
}

__global__ void __launch_bounds__(THREADS, 3)
nam_main(const float* __restrict__ x,  const float* __restrict__ W1,
         const float* __restrict__ b1, const float* __restrict__ W2,
         const float* __restrict__ b2, const float* __restrict__ W3)
{
    __shared__ SmemBuf sb[2];

    const int tid  = threadIdx.x;
    const int rowA = blockIdx.x * ROWS_PER_BLOCK + tid;           // rows strided by 128
    const int rowB = rowA + THREADS;
    const int f0   = blockIdx.y * FEATS_PER_CHUNK;
    const float* xrowA = x + (long)rowA * NFEAT + f0;
    const float* xrowB = x + (long)rowB * NFEAT + f0;

    // prologue: stage feature f0 into buffer 0
    stage(sb[0], W1 + f0 * H1DIM, b1 + f0 * H1DIM, W2 + (long)f0 * W2SZ,
          b2 + f0 * H2DIM, W3 + f0 * H2DIM, tid);
    __syncthreads();

    float accA = 0.0f, accB = 0.0f;
    #pragma unroll 1
    for (int k = 0; k < FEATS_PER_CHUNK; ++k) {
        // stage next feature into the other buffer (hidden under compute)
        if (k + 1 < FEATS_PER_CHUNK) {
            int f = f0 + k + 1;
            stage(sb[(k + 1) & 1], W1 + f * H1DIM, b1 + f * H1DIM,
                  W2 + (long)f * W2SZ, b2 + f * H2DIM, W3 + f * H2DIM, tid);
        }
        float ra, rb;
        feat_eval2(sb[k & 1], xrowA[k], xrowB[k], ra, rb);
        accA += ra;
        accB += rb;
        __syncthreads();
    }

    g_partial[blockIdx.y][rowA] = accA;
    g_partial[blockIdx.y][rowB] = accB;
}

__global__ void nam_reduce(const float* __restrict__ bias, float* __restrict__ out)
{
    int b = blockIdx.x * 256 + threadIdx.x;
    if (b < BATCH) {
        float s = bias[0];
        #pragma unroll
        for (int c = 0; c < FEAT_CHUNKS; ++c) s += g_partial[c][b];
        out[b] = 1.0f / (1.0f + expf(-s));
    }
}

extern "C" void kernel_launch(void* const* d_in, const int* in_sizes, int n_in,
                              void* d_out, int out_size)
{
    const float* x    = (const float*)d_in[0];  // [8192,256]
    const float* W1   = (const float*)d_in[1];  // [256,100]
    const float* b1   = (const float*)d_in[2];  // [256,100]
    const float* W2   = (const float*)d_in[3];  // [256,50,100]
    const float* b2   = (const float*)d_in[4];  // [256,50]
    const float* W3   = (const float*)d_in[5];  // [256,50]
    const float* bias = (const float*)d_in[6];  // [1]
    float* out = (float*)d_out;                 // [8192]

    dim3 grid(ROW_TILES, FEAT_CHUNKS);
    nam_main<<<grid, THREADS>>>(x, W1, b1, W2, b2, W3);
    nam_reduce<<<BATCH / 256, 256>>>(bias, out);
}